// round 13
// baseline (speedup 1.0000x reference)
#include <cuda_runtime.h>
#include <cuda_fp16.h>
#include <cstdint>

#define N_NODES 10000
#define N_EDGES 640000
#define E_TOT   (N_EDGES + N_NODES)   // 650000
#define H 128
#define NUM_LAYERS 4

#define TE 128
#define NT_TILES ((E_TOT + TE - 1) / TE)   // 5079
#define GRID_EDGE 148
#define THREADS_EDGE 384                   // 8 consumer warps + 4 producer warps

#define LDW 136   // half elems, W tile [n][k]
#define LDZ 136   // half elems, Z tiles [e][k]
#define LDD 132   // f32 elems,  D tile  [e][n]

// SMEM byte offsets
#define O_W   0u
#define O_Z0  34816u
#define ZBUF_BYTES 34816u                  // 128*LDZ*2, two buffers
#define O_D   104448u
#define O_DST 172032u                      // [2][128] ints
#define O_BIAS 173056u
#define SMEM_EDGE_BYTES 173568u

#define NEG_INF -3.4028234663852886e38f

// ---------------- persistent scratch ----------------
__device__ float g_buf0[N_NODES * H];
__device__ float g_buf1[N_NODES * H];
__device__ float g_A[N_NODES * H];
__device__ float g_B[N_NODES * H];
__device__ int   g_es0[E_TOT];
__device__ int   g_ed0[E_TOT];
__device__ int   g_es[E_TOT];   // sorted by dst
__device__ int   g_ed[E_TOT];   // sorted by dst
__device__ int   g_cnt[N_NODES];
__device__ int   g_pos[N_NODES];
__device__ int   g_is64;

// ---------------- mma/ldmatrix helpers ----------------
__device__ __forceinline__ void ldsm_x4(uint32_t& r0, uint32_t& r1, uint32_t& r2,
                                        uint32_t& r3, uint32_t addr) {
    asm volatile("ldmatrix.sync.aligned.m8n8.x4.shared.b16 {%0,%1,%2,%3}, [%4];"
                 : "=r"(r0), "=r"(r1), "=r"(r2), "=r"(r3) : "r"(addr));
}
__device__ __forceinline__ void mma16816(float* d, uint32_t a0, uint32_t a1, uint32_t a2,
                                         uint32_t a3, uint32_t b0, uint32_t b1) {
    asm volatile(
        "mma.sync.aligned.m16n8k16.row.col.f32.f16.f16.f32 "
        "{%0,%1,%2,%3}, {%4,%5,%6,%7}, {%8,%9}, {%0,%1,%2,%3};"
        : "+f"(d[0]), "+f"(d[1]), "+f"(d[2]), "+f"(d[3])
        : "r"(a0), "r"(a1), "r"(a2), "r"(a3), "r"(b0), "r"(b1));
}

__device__ __forceinline__ void atomic_fmax(float* p, float v) {
    if (v >= 0.f) atomicMax((int*)p, __float_as_int(v));
    else          atomicMin((unsigned int*)p, __float_as_uint(v));
}

// ---------------- edge dtype detect ----------------
__global__ void detect_dtype(const int* __restrict__ ei32) {
    __shared__ int sbad;
    if (threadIdx.x == 0) sbad = 0;
    __syncthreads();
    int bad = 0;
    for (int i = threadIdx.x; i < 1024; i += 256)
        if (ei32[2 * i + 1] != 0) bad = 1;
    if (bad) atomicOr(&sbad, 1);
    __syncthreads();
    if (threadIdx.x == 0) g_is64 = sbad ? 0 : 1;
}

__global__ void zero_cnt() {
    int i = blockIdx.x * blockDim.x + threadIdx.x;
    if (i < N_NODES) g_cnt[i] = 0;
}

// edge prep + histogram of dst
__global__ void prep_edges(const void* __restrict__ ei) {
    int i = blockIdx.x * blockDim.x + threadIdx.x;
    if (i < N_EDGES) {
        int s, d;
        if (g_is64) {
            const long long* p = (const long long*)ei;
            s = (int)p[i];
            d = (int)p[N_EDGES + i];
        } else {
            const int* p = (const int*)ei;
            s = p[i];
            d = p[N_EDGES + i];
        }
        g_es0[i] = s;
        g_ed0[i] = d;
        atomicAdd(&g_cnt[d], 1);
    } else if (i < E_TOT) {
        int n = i - N_EDGES;
        g_es0[i] = n;
        g_ed0[i] = n;
        atomicAdd(&g_cnt[n], 1);
    }
}

// single-block exclusive scan of g_cnt -> g_pos
__global__ void scan_kernel() {
    __shared__ int part[1024];
    int t = threadIdx.x;
    int s = 0;
    int base = t * 10;
    if (t < 1000) {
#pragma unroll
        for (int i = 0; i < 10; i++) s += g_cnt[base + i];
    }
    part[t] = s;
    __syncthreads();
    for (int off = 1; off < 1024; off <<= 1) {
        int v = part[t];
        if (t >= off) v += part[t - off];
        __syncthreads();
        part[t] = v;
        __syncthreads();
    }
    int excl = (t == 0) ? 0 : part[t - 1];
    if (t < 1000) {
        int run = excl;
#pragma unroll
        for (int i = 0; i < 10; i++) {
            int c = g_cnt[base + i];
            g_pos[base + i] = run;
            run += c;
        }
    }
}

__global__ void scatter_kernel() {
    int i = blockIdx.x * blockDim.x + threadIdx.x;
    if (i < E_TOT) {
        int d = g_ed0[i];
        int p = atomicAdd(&g_pos[d], 1);
        g_es[p] = g_es0[i];
        g_ed[p] = d;
    }
}

// ---------------- embed: h0 = x@W_emb + b ----------------
__global__ void embed_kernel(const float* __restrict__ x, const float* __restrict__ W,
                             const float* __restrict__ b, float* __restrict__ h) {
    __shared__ float sx[16][64];
    int n0 = blockIdx.x * 16;
    for (int i = threadIdx.x; i < 16 * 64; i += 128)
        sx[i >> 6][i & 63] = x[n0 * 64 + i];
    __syncthreads();
    int c = threadIdx.x;
    float bc = b[c];
    for (int n = 0; n < 16; n++) {
        float acc = bc;
#pragma unroll 16
        for (int k = 0; k < 64; k++) acc = fmaf(sx[n][k], W[k * 128 + c], acc);
        h[(n0 + n) * 128 + c] = acc;
    }
}

// ---------------- node transform (256 thr): A = h(W1a-W1b)+b1, B = h W1b ----------------
__global__ void node_transform(const float* __restrict__ h, const float* __restrict__ W1l,
                               const float* __restrict__ b1l, float* __restrict__ A,
                               float* __restrict__ B, float* __restrict__ out_init) {
    __shared__ float sh[16][128];
    int n0 = blockIdx.x * 16;
    for (int i = threadIdx.x; i < 16 * 128; i += 256)
        sh[i >> 7][i & 127] = h[n0 * 128 + i];
    __syncthreads();
    int c = threadIdx.x & 127;
    int nh = (threadIdx.x >> 7) * 8;   // node half: 0 or 8
    float a[8], bb[8];
    float bc = b1l[c];
#pragma unroll
    for (int n = 0; n < 8; n++) { a[n] = bc; bb[n] = 0.f; }
    for (int k = 0; k < 128; k++) {
        float wa = W1l[k * 128 + c];
        float wb = W1l[(k + 128) * 128 + c];
        float wd = wa - wb;
#pragma unroll
        for (int n = 0; n < 8; n++) {
            float hv = sh[nh + n][k];
            a[n]  = fmaf(hv, wd, a[n]);
            bb[n] = fmaf(hv, wb, bb[n]);
        }
    }
#pragma unroll
    for (int n = 0; n < 8; n++) {
        int r = (n0 + nh + n) * 128 + c;
        A[r] = a[n];
        B[r] = bb[n];
        out_init[r] = NEG_INF;
    }
}

// ---------------- persistent edge phase: producers own epilogue+build ----------------
__global__ __launch_bounds__(THREADS_EDGE, 1)
void edge_persist(const float* __restrict__ A, const float* __restrict__ B,
                  const float* __restrict__ W2l, const float* __restrict__ b2l,
                  const int* __restrict__ es, const int* __restrict__ ed,
                  float* __restrict__ hout) {
    extern __shared__ __align__(16) char sm[];
    __half* sW   = (__half*)(sm + O_W);
    float* sD    = (float*)(sm + O_D);
    int*   sDst  = (int*)(sm + O_DST);     // [2][128]
    float* sBias = (float*)(sm + O_BIAS);

    int tid = threadIdx.x;
    int lane = tid & 31;
    int w = tid >> 5;

    uint32_t smb = (uint32_t)__cvta_generic_to_shared(sm);

    // one-time: W2^T into fp16: sW[n][k]
    for (int i = tid; i < H * H; i += THREADS_EDGE) {
        int k = i >> 7, n = i & 127;
        sW[n * LDW + k] = __float2half_rn(W2l[i]);
    }
    if (tid < 128) sBias[tid] = b2l[tid];
    __syncthreads();

    bool is_consumer = (w < 8);

    // consumer mapping: er = w>>1 edges [er*32,+32); nc = w&1 cols [nc*64,+64)
    int er = w >> 1;
    int nc = w & 1;
    int g  = lane >> 2;
    int t2 = (lane & 3) * 2;

    // A ldmatrix lane addresses
    uint32_t aoff0 = ((uint32_t)((er * 32 + (lane & 15)) * LDZ + (lane >> 4) * 8)) * 2u;
    uint32_t aoff1 = aoff0 + 16u * LDZ * 2u;
    // B x4 lane addresses: lanes 0-15 -> j slab, lanes 16-31 -> j+1 slab (+8 rows)
    uint32_t brow4 = (uint32_t)(nc * 64 + (lane & 7) + ((lane >> 4) & 1) * 8);
    uint32_t bkh   = (uint32_t)((lane >> 3) & 1) * 8u;
    uint32_t bwoff = smb + O_W + (brow4 * LDW + bkh) * 2u;

    // producer identity: threads 256..383 -> 128 producers, 1 per edge
    int pe = tid - 256;

    auto build = [&](int t, int buf) {
        int ee = t * TE + pe;
        bool vld = ee < E_TOT;
        int d = vld ? __ldg(&ed[ee]) : 0;
        int s = vld ? __ldg(&es[ee]) : 0;
        sDst[buf * 128 + pe] = vld ? d : -1;
        const float4* pa = (const float4*)(A + (size_t)d * 128);
        const float4* pb = (const float4*)(B + (size_t)s * 128);
        __half* sZ = (__half*)(sm + O_Z0 + (uint32_t)buf * ZBUF_BYTES);
#pragma unroll
        for (int i = 0; i < 16; i++) {
            float4 a0 = __ldg(pa + 2 * i), a1 = __ldg(pa + 2 * i + 1);
            float4 b0 = __ldg(pb + 2 * i), b1 = __ldg(pb + 2 * i + 1);
            float v0 = 0.f, v1 = 0.f, v2 = 0.f, v3 = 0.f;
            float v4 = 0.f, v5 = 0.f, v6 = 0.f, v7 = 0.f;
            if (vld) {
                v0 = fmaxf(a0.x + b0.x, 0.f);
                v1 = fmaxf(a0.y + b0.y, 0.f);
                v2 = fmaxf(a0.z + b0.z, 0.f);
                v3 = fmaxf(a0.w + b0.w, 0.f);
                v4 = fmaxf(a1.x + b1.x, 0.f);
                v5 = fmaxf(a1.y + b1.y, 0.f);
                v6 = fmaxf(a1.z + b1.z, 0.f);
                v7 = fmaxf(a1.w + b1.w, 0.f);
            }
            __half2 h0 = __floats2half2_rn(v0, v1);
            __half2 h1 = __floats2half2_rn(v2, v3);
            __half2 h2 = __floats2half2_rn(v4, v5);
            __half2 h3 = __floats2half2_rn(v6, v7);
            uint4 pk;
            pk.x = *(uint32_t*)&h0;
            pk.y = *(uint32_t*)&h1;
            pk.z = *(uint32_t*)&h2;
            pk.w = *(uint32_t*)&h3;
            *(uint4*)(sZ + pe * LDZ + i * 8) = pk;
        }
    };

    // producer epilogue: 128 thr, 4 channels (float4) x 32-edge quarter each
    auto epilogue_p = [&](int buf) {
        int cq = pe & 31;           // channel quad, c = cq*4
        int qq = pe >> 5;           // 0..3
        float4 bias4 = *(float4*)(sBias + cq * 4);
        const int* dstb = sDst + buf * 128;
        int cur = dstb[32 * qq];
        float r0 = NEG_INF, r1 = NEG_INF, r2 = NEG_INF, r3 = NEG_INF;
#pragma unroll 4
        for (int ee = 32 * qq; ee < 32 * qq + 32; ee++) {
            int d = dstb[ee];
            float4 v = *(float4*)(sD + ee * LDD + cq * 4);
            v.x += bias4.x; v.y += bias4.y; v.z += bias4.z; v.w += bias4.w;
            if (d != cur) {
                if (cur >= 0) {
                    float* p = hout + (size_t)cur * 128 + cq * 4;
                    atomic_fmax(p, r0); atomic_fmax(p + 1, r1);
                    atomic_fmax(p + 2, r2); atomic_fmax(p + 3, r3);
                }
                cur = d;
                r0 = v.x; r1 = v.y; r2 = v.z; r3 = v.w;
            } else {
                r0 = fmaxf(r0, v.x); r1 = fmaxf(r1, v.y);
                r2 = fmaxf(r2, v.z); r3 = fmaxf(r3, v.w);
            }
        }
        if (cur >= 0) {
            float* p = hout + (size_t)cur * 128 + cq * 4;
            atomic_fmax(p, r0); atomic_fmax(p + 1, r1);
            atomic_fmax(p + 2, r2); atomic_fmax(p + 3, r3);
        }
    };

    // ---- prologue: build first tile into buf 0 ----
    if (!is_consumer && blockIdx.x < NT_TILES) build(blockIdx.x, 0);
    __syncthreads();

    if (is_consumer) {
        float acc[2][8][4];
        int it = 0;
        for (int t = blockIdx.x; t < NT_TILES; t += GRID_EDGE, it++) {
            int p = it & 1;
            // phase 1: compute gemm(t) into regs
            uint32_t zbase = smb + O_Z0 + (uint32_t)p * ZBUF_BYTES;
#pragma unroll
            for (int f = 0; f < 2; f++)
#pragma unroll
                for (int j = 0; j < 8; j++)
#pragma unroll
                    for (int r = 0; r < 4; r++) acc[f][j][r] = 0.f;
#pragma unroll
            for (int k0 = 0; k0 < 8; k0++) {
                uint32_t a0[4], a1[4];
                ldsm_x4(a0[0], a0[1], a0[2], a0[3], zbase + aoff0 + (uint32_t)k0 * 32u);
                ldsm_x4(a1[0], a1[1], a1[2], a1[3], zbase + aoff1 + (uint32_t)k0 * 32u);
#pragma unroll
                for (int j = 0; j < 8; j += 2) {
                    uint32_t jb = (uint32_t)(j * 8 * LDW * 2) + (uint32_t)k0 * 32u;
                    uint32_t b0, b1, b2, b3;
                    ldsm_x4(b0, b1, b2, b3, bwoff + jb);
                    mma16816(acc[0][j], a0[0], a0[1], a0[2], a0[3], b0, b1);
                    mma16816(acc[1][j], a1[0], a1[1], a1[2], a1[3], b0, b1);
                    mma16816(acc[0][j + 1], a0[0], a0[1], a0[2], a0[3], b2, b3);
                    mma16816(acc[1][j + 1], a1[0], a1[1], a1[2], a1[3], b2, b3);
                }
            }
            __syncthreads();          // (1) epilogue(t-1) done -> sD free
            // phase 2: store acc -> sD
#pragma unroll
            for (int f = 0; f < 2; f++) {
                int r0 = er * 32 + f * 16 + g;
#pragma unroll
                for (int j = 0; j < 8; j++) {
                    int c = nc * 64 + j * 8 + t2;
                    *(float2*)(sD + r0 * LDD + c)       = make_float2(acc[f][j][0], acc[f][j][1]);
                    *(float2*)(sD + (r0 + 8) * LDD + c) = make_float2(acc[f][j][2], acc[f][j][3]);
                }
            }
            __syncthreads();          // (2) sD(t) ready for epilogue(t)
        }
    } else {
        int it = 0;
        int last_p = -1;
        for (int t = blockIdx.x; t < NT_TILES; t += GRID_EDGE, it++) {
            int p = it & 1;
            // phase 1: epilogue(t-1), then build(t+1)
            if (it > 0) epilogue_p(1 - p);
            asm volatile("bar.sync 2, 128;" ::: "memory");   // sDst[1-p] reads done
            int tn = t + GRID_EDGE;
            if (tn < NT_TILES) build(tn, 1 - p);
            __syncthreads();          // (1)
            __syncthreads();          // (2) sD(t) now stored
            last_p = p;
        }
        if (last_p >= 0) epilogue_p(last_p);   // trailing epilogue for final tile
    }
}

// ---------------- final: out = h@W_fc + b ----------------
__global__ void final_kernel(const float* __restrict__ h, const float* __restrict__ W,
                             const float* __restrict__ b, float* __restrict__ out) {
    __shared__ float sh[16][128];
    int n0 = blockIdx.x * 16;
    for (int i = threadIdx.x; i < 16 * 128; i += 128)
        sh[i >> 7][i & 127] = h[n0 * 128 + i];
    __syncthreads();
    int c = threadIdx.x;
    float bc = b[c];
    for (int n = 0; n < 16; n++) {
        float acc = bc;
#pragma unroll 8
        for (int k = 0; k < 128; k++) acc = fmaf(sh[n][k], W[k * 128 + c], acc);
        out[(n0 + n) * 128 + c] = acc;
    }
}

extern "C" void kernel_launch(void* const* d_in, const int* in_sizes, int n_in,
                              void* d_out, int out_size) {
    const float* x    = (const float*)d_in[0];
    const void*  ei   = d_in[1];
    const float* Wemb = (const float*)d_in[2];
    const float* bemb = (const float*)d_in[3];
    const float* W1   = (const float*)d_in[4];
    const float* b1   = (const float*)d_in[5];
    const float* W2   = (const float*)d_in[6];
    const float* b2   = (const float*)d_in[7];
    const float* Wfc  = (const float*)d_in[8];
    const float* bfc  = (const float*)d_in[9];
    float* out = (float*)d_out;

    float *buf0, *buf1, *Ap, *Bp;
    int *es, *ed;
    cudaGetSymbolAddress((void**)&buf0, g_buf0);
    cudaGetSymbolAddress((void**)&buf1, g_buf1);
    cudaGetSymbolAddress((void**)&Ap,   g_A);
    cudaGetSymbolAddress((void**)&Bp,   g_B);
    cudaGetSymbolAddress((void**)&es,   g_es);
    cudaGetSymbolAddress((void**)&ed,   g_ed);

    cudaFuncSetAttribute(edge_persist, cudaFuncAttributeMaxDynamicSharedMemorySize,
                         SMEM_EDGE_BYTES);

    detect_dtype<<<1, 256>>>((const int*)ei);
    zero_cnt<<<(N_NODES + 255) / 256, 256>>>();
    prep_edges<<<(E_TOT + 255) / 256, 256>>>(ei);
    scan_kernel<<<1, 1024>>>();
    scatter_kernel<<<(E_TOT + 255) / 256, 256>>>();
    embed_kernel<<<N_NODES / 16, 128>>>(x, Wemb, bemb, buf0);

    float* hin = buf0;
    float* hout = buf1;
    for (int l = 0; l < NUM_LAYERS; l++) {
        node_transform<<<N_NODES / 16, 256>>>(hin, W1 + l * 2 * H * H, b1 + l * H,
                                              Ap, Bp, hout);
        edge_persist<<<GRID_EDGE, THREADS_EDGE, SMEM_EDGE_BYTES>>>(Ap, Bp, W2 + l * H * H,
                                                                   b2 + l * H, es, ed, hout);
        float* t = hin; hin = hout; hout = t;
    }
    final_kernel<<<N_NODES / 16, 128>>>(hin, Wfc, bfc, out);
}

// round 14
// speedup vs baseline: 1.0054x; 1.0054x over previous
#include <cuda_runtime.h>
#include <cuda_fp16.h>
#include <cstdint>

#define N_NODES 10000
#define N_EDGES 640000
#define E_TOT   (N_EDGES + N_NODES)   // 650000
#define H 128
#define NUM_LAYERS 4

#define TE 128
#define NT_TILES ((E_TOT + TE - 1) / TE)   // 5079
#define GRID_EDGE 148
#define THREADS_EDGE 512                   // 8 consumer warps + 8 producer warps

#define LDW 136   // half elems, W tile [n][k]
#define LDZ 136   // half elems, Z tiles [e][k]
#define LDD 132   // f32 elems,  D tile  [e][n]

// SMEM byte offsets
#define O_W   0u
#define O_Z0  34816u
#define ZBUF_BYTES 34816u                  // 128*LDZ*2, two buffers
#define O_D   104448u
#define O_DST 172032u                      // [2][128] ints
#define O_BIAS 173056u
#define SMEM_EDGE_BYTES 173568u

#define NEG_INF -3.4028234663852886e38f

// ---------------- persistent scratch ----------------
__device__ float g_buf0[N_NODES * H];
__device__ float g_buf1[N_NODES * H];
__device__ float g_A[N_NODES * H];
__device__ float g_B[N_NODES * H];
__device__ int   g_es0[E_TOT];
__device__ int   g_ed0[E_TOT];
__device__ int   g_es[E_TOT];   // sorted by dst
__device__ int   g_ed[E_TOT];   // sorted by dst
__device__ int   g_cnt[N_NODES];
__device__ int   g_pos[N_NODES];
__device__ int   g_is64;

// ---------------- mma/ldmatrix helpers ----------------
__device__ __forceinline__ void ldsm_x4(uint32_t& r0, uint32_t& r1, uint32_t& r2,
                                        uint32_t& r3, uint32_t addr) {
    asm volatile("ldmatrix.sync.aligned.m8n8.x4.shared.b16 {%0,%1,%2,%3}, [%4];"
                 : "=r"(r0), "=r"(r1), "=r"(r2), "=r"(r3) : "r"(addr));
}
__device__ __forceinline__ void mma16816(float* d, uint32_t a0, uint32_t a1, uint32_t a2,
                                         uint32_t a3, uint32_t b0, uint32_t b1) {
    asm volatile(
        "mma.sync.aligned.m16n8k16.row.col.f32.f16.f16.f32 "
        "{%0,%1,%2,%3}, {%4,%5,%6,%7}, {%8,%9}, {%0,%1,%2,%3};"
        : "+f"(d[0]), "+f"(d[1]), "+f"(d[2]), "+f"(d[3])
        : "r"(a0), "r"(a1), "r"(a2), "r"(a3), "r"(b0), "r"(b1));
}

__device__ __forceinline__ void atomic_fmax(float* p, float v) {
    if (v >= 0.f) atomicMax((int*)p, __float_as_int(v));
    else          atomicMin((unsigned int*)p, __float_as_uint(v));
}

// ---------------- edge dtype detect ----------------
__global__ void detect_dtype(const int* __restrict__ ei32) {
    __shared__ int sbad;
    if (threadIdx.x == 0) sbad = 0;
    __syncthreads();
    int bad = 0;
    for (int i = threadIdx.x; i < 1024; i += 256)
        if (ei32[2 * i + 1] != 0) bad = 1;
    if (bad) atomicOr(&sbad, 1);
    __syncthreads();
    if (threadIdx.x == 0) g_is64 = sbad ? 0 : 1;
}

__global__ void zero_cnt() {
    int i = blockIdx.x * blockDim.x + threadIdx.x;
    if (i < N_NODES) g_cnt[i] = 0;
}

// edge prep + histogram of dst
__global__ void prep_edges(const void* __restrict__ ei) {
    int i = blockIdx.x * blockDim.x + threadIdx.x;
    if (i < N_EDGES) {
        int s, d;
        if (g_is64) {
            const long long* p = (const long long*)ei;
            s = (int)p[i];
            d = (int)p[N_EDGES + i];
        } else {
            const int* p = (const int*)ei;
            s = p[i];
            d = p[N_EDGES + i];
        }
        g_es0[i] = s;
        g_ed0[i] = d;
        atomicAdd(&g_cnt[d], 1);
    } else if (i < E_TOT) {
        int n = i - N_EDGES;
        g_es0[i] = n;
        g_ed0[i] = n;
        atomicAdd(&g_cnt[n], 1);
    }
}

// single-block exclusive scan of g_cnt -> g_pos
__global__ void scan_kernel() {
    __shared__ int part[1024];
    int t = threadIdx.x;
    int s = 0;
    int base = t * 10;
    if (t < 1000) {
#pragma unroll
        for (int i = 0; i < 10; i++) s += g_cnt[base + i];
    }
    part[t] = s;
    __syncthreads();
    for (int off = 1; off < 1024; off <<= 1) {
        int v = part[t];
        if (t >= off) v += part[t - off];
        __syncthreads();
        part[t] = v;
        __syncthreads();
    }
    int excl = (t == 0) ? 0 : part[t - 1];
    if (t < 1000) {
        int run = excl;
#pragma unroll
        for (int i = 0; i < 10; i++) {
            int c = g_cnt[base + i];
            g_pos[base + i] = run;
            run += c;
        }
    }
}

__global__ void scatter_kernel() {
    int i = blockIdx.x * blockDim.x + threadIdx.x;
    if (i < E_TOT) {
        int d = g_ed0[i];
        int p = atomicAdd(&g_pos[d], 1);
        g_es[p] = g_es0[i];
        g_ed[p] = d;
    }
}

// ---------------- embed: h0 = x@W_emb + b ----------------
__global__ void embed_kernel(const float* __restrict__ x, const float* __restrict__ W,
                             const float* __restrict__ b, float* __restrict__ h) {
    __shared__ float sx[16][64];
    int n0 = blockIdx.x * 16;
    for (int i = threadIdx.x; i < 16 * 64; i += 128)
        sx[i >> 6][i & 63] = x[n0 * 64 + i];
    __syncthreads();
    int c = threadIdx.x;
    float bc = b[c];
    for (int n = 0; n < 16; n++) {
        float acc = bc;
#pragma unroll 16
        for (int k = 0; k < 64; k++) acc = fmaf(sx[n][k], W[k * 128 + c], acc);
        h[(n0 + n) * 128 + c] = acc;
    }
}

// ---------------- node transform (256 thr): A = h(W1a-W1b)+b1, B = h W1b ----------------
__global__ void node_transform(const float* __restrict__ h, const float* __restrict__ W1l,
                               const float* __restrict__ b1l, float* __restrict__ A,
                               float* __restrict__ B, float* __restrict__ out_init) {
    __shared__ float sh[16][128];
    int n0 = blockIdx.x * 16;
    for (int i = threadIdx.x; i < 16 * 128; i += 256)
        sh[i >> 7][i & 127] = h[n0 * 128 + i];
    __syncthreads();
    int c = threadIdx.x & 127;
    int nh = (threadIdx.x >> 7) * 8;   // node half: 0 or 8
    float a[8], bb[8];
    float bc = b1l[c];
#pragma unroll
    for (int n = 0; n < 8; n++) { a[n] = bc; bb[n] = 0.f; }
    for (int k = 0; k < 128; k++) {
        float wa = W1l[k * 128 + c];
        float wb = W1l[(k + 128) * 128 + c];
        float wd = wa - wb;
#pragma unroll
        for (int n = 0; n < 8; n++) {
            float hv = sh[nh + n][k];
            a[n]  = fmaf(hv, wd, a[n]);
            bb[n] = fmaf(hv, wb, bb[n]);
        }
    }
#pragma unroll
    for (int n = 0; n < 8; n++) {
        int r = (n0 + nh + n) * 128 + c;
        A[r] = a[n];
        B[r] = bb[n];
        out_init[r] = NEG_INF;
    }
}

// ---------------- persistent edge phase: 8 consumer + 8 producer warps ----------------
__global__ __launch_bounds__(THREADS_EDGE, 1)
void edge_persist(const float* __restrict__ A, const float* __restrict__ B,
                  const float* __restrict__ W2l, const float* __restrict__ b2l,
                  const int* __restrict__ es, const int* __restrict__ ed,
                  float* __restrict__ hout) {
    extern __shared__ __align__(16) char sm[];
    __half* sW   = (__half*)(sm + O_W);
    float* sD    = (float*)(sm + O_D);
    int*   sDst  = (int*)(sm + O_DST);     // [2][128]
    float* sBias = (float*)(sm + O_BIAS);

    int tid = threadIdx.x;
    int lane = tid & 31;
    int w = tid >> 5;

    uint32_t smb = (uint32_t)__cvta_generic_to_shared(sm);

    // one-time: W2^T into fp16: sW[n][k]
    for (int i = tid; i < H * H; i += THREADS_EDGE) {
        int k = i >> 7, n = i & 127;
        sW[n * LDW + k] = __float2half_rn(W2l[i]);
    }
    if (tid < 128) sBias[tid] = b2l[tid];
    __syncthreads();

    bool is_consumer = (w < 8);

    // consumer mapping: er = w>>1 edges [er*32,+32); nc = w&1 cols [nc*64,+64)
    int er = w >> 1;
    int nc = w & 1;
    int g  = lane >> 2;
    int t2 = (lane & 3) * 2;

    // A ldmatrix lane addresses
    uint32_t aoff0 = ((uint32_t)((er * 32 + (lane & 15)) * LDZ + (lane >> 4) * 8)) * 2u;
    uint32_t aoff1 = aoff0 + 16u * LDZ * 2u;
    // B x4 lane addresses: lanes 0-15 -> j slab, lanes 16-31 -> j+1 slab (+8 rows)
    uint32_t brow4 = (uint32_t)(nc * 64 + (lane & 7) + ((lane >> 4) & 1) * 8);
    uint32_t bkh   = (uint32_t)((lane >> 3) & 1) * 8u;
    uint32_t bwoff = smb + O_W + (brow4 * LDW + bkh) * 2u;

    // producer identity: threads 256..511
    int pt = tid - 256;       // 0..255
    int pe = pt >> 1;         // edge 0..127 (2 threads/edge)
    int pq = pt & 1;          // channel half [pq*64, +64)

    auto build = [&](int t, int buf) {
        int ee = t * TE + pe;
        bool vld = ee < E_TOT;
        int d = vld ? __ldg(&ed[ee]) : 0;
        int s = vld ? __ldg(&es[ee]) : 0;
        if (pq == 0) sDst[buf * 128 + pe] = vld ? d : -1;
        const float4* pa = (const float4*)(A + (size_t)d * 128 + pq * 64);
        const float4* pb = (const float4*)(B + (size_t)s * 128 + pq * 64);
        __half* sZ = (__half*)(sm + O_Z0 + (uint32_t)buf * ZBUF_BYTES);
#pragma unroll
        for (int i = 0; i < 8; i++) {
            float4 a0 = __ldg(pa + 2 * i), a1 = __ldg(pa + 2 * i + 1);
            float4 b0 = __ldg(pb + 2 * i), b1 = __ldg(pb + 2 * i + 1);
            float v0 = 0.f, v1 = 0.f, v2 = 0.f, v3 = 0.f;
            float v4 = 0.f, v5 = 0.f, v6 = 0.f, v7 = 0.f;
            if (vld) {
                v0 = fmaxf(a0.x + b0.x, 0.f);
                v1 = fmaxf(a0.y + b0.y, 0.f);
                v2 = fmaxf(a0.z + b0.z, 0.f);
                v3 = fmaxf(a0.w + b0.w, 0.f);
                v4 = fmaxf(a1.x + b1.x, 0.f);
                v5 = fmaxf(a1.y + b1.y, 0.f);
                v6 = fmaxf(a1.z + b1.z, 0.f);
                v7 = fmaxf(a1.w + b1.w, 0.f);
            }
            __half2 h0 = __floats2half2_rn(v0, v1);
            __half2 h1 = __floats2half2_rn(v2, v3);
            __half2 h2 = __floats2half2_rn(v4, v5);
            __half2 h3 = __floats2half2_rn(v6, v7);
            uint4 pk;
            pk.x = *(uint32_t*)&h0;
            pk.y = *(uint32_t*)&h1;
            pk.z = *(uint32_t*)&h2;
            pk.w = *(uint32_t*)&h3;
            *(uint4*)(sZ + pe * LDZ + pq * 64 + i * 8) = pk;
        }
    };

    // producer epilogue: 256 thr = 64 channel-pairs x 4 quarters of 32 edges
    auto epilogue_p = [&](int buf) {
        int cp = pt & 63;
        int qq = pt >> 6;           // 0..3
        float2 bias2 = *(float2*)(sBias + cp * 2);
        const int* dstb = sDst + buf * 128;
        int cur = dstb[32 * qq];
        float r0 = NEG_INF, r1 = NEG_INF;
#pragma unroll 4
        for (int ee = 32 * qq; ee < 32 * qq + 32; ee++) {
            int d = dstb[ee];
            float2 v = *(float2*)(sD + ee * LDD + cp * 2);
            v.x += bias2.x;
            v.y += bias2.y;
            if (d != cur) {
                if (cur >= 0) {
                    float* p = hout + (size_t)cur * 128 + cp * 2;
                    atomic_fmax(p, r0);
                    atomic_fmax(p + 1, r1);
                }
                cur = d;
                r0 = v.x;
                r1 = v.y;
            } else {
                r0 = fmaxf(r0, v.x);
                r1 = fmaxf(r1, v.y);
            }
        }
        if (cur >= 0) {
            float* p = hout + (size_t)cur * 128 + cp * 2;
            atomic_fmax(p, r0);
            atomic_fmax(p + 1, r1);
        }
    };

    // ---- prologue: build first tile into buf 0 ----
    if (!is_consumer) build(blockIdx.x, 0);
    __syncthreads();

    if (is_consumer) {
        float acc[2][8][4];
        int it = 0;
        for (int t = blockIdx.x; t < NT_TILES; t += GRID_EDGE, it++) {
            int p = it & 1;
            // phase A: compute gemm(t) into regs
            uint32_t zbase = smb + O_Z0 + (uint32_t)p * ZBUF_BYTES;
#pragma unroll
            for (int f = 0; f < 2; f++)
#pragma unroll
                for (int j = 0; j < 8; j++)
#pragma unroll
                    for (int r = 0; r < 4; r++) acc[f][j][r] = 0.f;
#pragma unroll
            for (int k0 = 0; k0 < 8; k0++) {
                uint32_t a0[4], a1[4];
                ldsm_x4(a0[0], a0[1], a0[2], a0[3], zbase + aoff0 + (uint32_t)k0 * 32u);
                ldsm_x4(a1[0], a1[1], a1[2], a1[3], zbase + aoff1 + (uint32_t)k0 * 32u);
#pragma unroll
                for (int j = 0; j < 8; j += 2) {
                    uint32_t jb = (uint32_t)(j * 8 * LDW * 2) + (uint32_t)k0 * 32u;
                    uint32_t b0, b1, b2, b3;
                    ldsm_x4(b0, b1, b2, b3, bwoff + jb);
                    mma16816(acc[0][j], a0[0], a0[1], a0[2], a0[3], b0, b1);
                    mma16816(acc[1][j], a1[0], a1[1], a1[2], a1[3], b0, b1);
                    mma16816(acc[0][j + 1], a0[0], a0[1], a0[2], a0[3], b2, b3);
                    mma16816(acc[1][j + 1], a1[0], a1[1], a1[2], a1[3], b2, b3);
                }
            }
            __syncthreads();          // (1) epilogue(t-1) done -> sD free
            // phase B: store acc -> sD
#pragma unroll
            for (int f = 0; f < 2; f++) {
                int r0 = er * 32 + f * 16 + g;
#pragma unroll
                for (int j = 0; j < 8; j++) {
                    int c = nc * 64 + j * 8 + t2;
                    *(float2*)(sD + r0 * LDD + c)       = make_float2(acc[f][j][0], acc[f][j][1]);
                    *(float2*)(sD + (r0 + 8) * LDD + c) = make_float2(acc[f][j][2], acc[f][j][3]);
                }
            }
            __syncthreads();          // (2) sD(t) ready
        }
    } else {
        int it = 0;
        int last_p = -1;
        for (int t = blockIdx.x; t < NT_TILES; t += GRID_EDGE, it++) {
            int p = it & 1;
            // phase A: epilogue(t-1) from sD, then build(t+1) into buf 1-p
            if (it > 0) epilogue_p(1 - p);
            asm volatile("bar.sync 2, 256;" ::: "memory");   // sDst/Z[1-p] reads done
            int tn = t + GRID_EDGE;
            if (tn < NT_TILES) build(tn, 1 - p);
            __syncthreads();          // (1)
            __syncthreads();          // (2) sD(t) stored by consumers
            last_p = p;
        }
        if (last_p >= 0) epilogue_p(last_p);   // trailing epilogue for final tile
    }
}

// ---------------- final: out = h@W_fc + b ----------------
__global__ void final_kernel(const float* __restrict__ h, const float* __restrict__ W,
                             const float* __restrict__ b, float* __restrict__ out) {
    __shared__ float sh[16][128];
    int n0 = blockIdx.x * 16;
    for (int i = threadIdx.x; i < 16 * 128; i += 128)
        sh[i >> 7][i & 127] = h[n0 * 128 + i];
    __syncthreads();
    int c = threadIdx.x;
    float bc = b[c];
    for (int n = 0; n < 16; n++) {
        float acc = bc;
#pragma unroll 8
        for (int k = 0; k < 128; k++) acc = fmaf(sh[n][k], W[k * 128 + c], acc);
        out[(n0 + n) * 128 + c] = acc;
    }
}

extern "C" void kernel_launch(void* const* d_in, const int* in_sizes, int n_in,
                              void* d_out, int out_size) {
    const float* x    = (const float*)d_in[0];
    const void*  ei   = d_in[1];
    const float* Wemb = (const float*)d_in[2];
    const float* bemb = (const float*)d_in[3];
    const float* W1   = (const float*)d_in[4];
    const float* b1   = (const float*)d_in[5];
    const float* W2   = (const float*)d_in[6];
    const float* b2   = (const float*)d_in[7];
    const float* Wfc  = (const float*)d_in[8];
    const float* bfc  = (const float*)d_in[9];
    float* out = (float*)d_out;

    float *buf0, *buf1, *Ap, *Bp;
    int *es, *ed;
    cudaGetSymbolAddress((void**)&buf0, g_buf0);
    cudaGetSymbolAddress((void**)&buf1, g_buf1);
    cudaGetSymbolAddress((void**)&Ap,   g_A);
    cudaGetSymbolAddress((void**)&Bp,   g_B);
    cudaGetSymbolAddress((void**)&es,   g_es);
    cudaGetSymbolAddress((void**)&ed,   g_ed);

    cudaFuncSetAttribute(edge_persist, cudaFuncAttributeMaxDynamicSharedMemorySize,
                         SMEM_EDGE_BYTES);

    detect_dtype<<<1, 256>>>((const int*)ei);
    zero_cnt<<<(N_NODES + 255) / 256, 256>>>();
    prep_edges<<<(E_TOT + 255) / 256, 256>>>(ei);
    scan_kernel<<<1, 1024>>>();
    scatter_kernel<<<(E_TOT + 255) / 256, 256>>>();
    embed_kernel<<<N_NODES / 16, 128>>>(x, Wemb, bemb, buf0);

    float* hin = buf0;
    float* hout = buf1;
    for (int l = 0; l < NUM_LAYERS; l++) {
        node_transform<<<N_NODES / 16, 256>>>(hin, W1 + l * 2 * H * H, b1 + l * H,
                                              Ap, Bp, hout);
        edge_persist<<<GRID_EDGE, THREADS_EDGE, SMEM_EDGE_BYTES>>>(Ap, Bp, W2 + l * H * H,
                                                                   b2 + l * H, es, ed, hout);
        float* t = hin; hin = hout; hout = t;
    }
    final_kernel<<<N_NODES / 16, 128>>>(hin, Wfc, bfc, out);
}

// round 17
// speedup vs baseline: 1.2174x; 1.2109x over previous
#include <cuda_runtime.h>
#include <cuda_fp16.h>
#include <cstdint>

#define N_NODES 10000
#define N_EDGES 640000
#define E_TOT   (N_EDGES + N_NODES)   // 650000
#define H 128
#define NUM_LAYERS 4

#define TE 128
#define NT_TILES ((E_TOT + TE - 1) / TE)   // 5079
#define GRID_EDGE 148
#define THREADS_EDGE 384                   // 8 consumer warps + 4 producer warps

#define LDW 136   // half elems, W tile [n][k]
#define LDZ 136   // half elems, Z tiles [e][k]
#define LDD 132   // f32 elems,  D tile  [e][n]

// SMEM byte offsets
#define O_W   0u
#define O_Z0  34816u
#define ZBUF_BYTES 34816u                  // 128*LDZ*2, two buffers
#define O_D   104448u
#define O_DST 172032u                      // [2][128] ints
#define O_BIAS 173056u
#define SMEM_EDGE_BYTES 173568u

#define NEG_INF -3.4028234663852886e38f

// ---------------- persistent scratch ----------------
__device__ float g_buf0[N_NODES * H];
__device__ float g_buf1[N_NODES * H];
__device__ float g_A[N_NODES * H];
__device__ float g_B[N_NODES * H];
__device__ int   g_es0[E_TOT];
__device__ int   g_ed0[E_TOT];
__device__ int   g_es[E_TOT];   // sorted by dst
__device__ int   g_ed[E_TOT];   // sorted by dst
__device__ int   g_cnt[N_NODES];
__device__ int   g_pos[N_NODES];
__device__ int   g_is64;

// ---------------- mma/ldmatrix helpers ----------------
__device__ __forceinline__ void ldsm_x4(uint32_t& r0, uint32_t& r1, uint32_t& r2,
                                        uint32_t& r3, uint32_t addr) {
    asm volatile("ldmatrix.sync.aligned.m8n8.x4.shared.b16 {%0,%1,%2,%3}, [%4];"
                 : "=r"(r0), "=r"(r1), "=r"(r2), "=r"(r3) : "r"(addr));
}
__device__ __forceinline__ void mma16816(float* d, uint32_t a0, uint32_t a1, uint32_t a2,
                                         uint32_t a3, uint32_t b0, uint32_t b1) {
    asm volatile(
        "mma.sync.aligned.m16n8k16.row.col.f32.f16.f16.f32 "
        "{%0,%1,%2,%3}, {%4,%5,%6,%7}, {%8,%9}, {%0,%1,%2,%3};"
        : "+f"(d[0]), "+f"(d[1]), "+f"(d[2]), "+f"(d[3])
        : "r"(a0), "r"(a1), "r"(a2), "r"(a3), "r"(b0), "r"(b1));
}

__device__ __forceinline__ void atomic_fmax(float* p, float v) {
    if (v >= 0.f) atomicMax((int*)p, __float_as_int(v));
    else          atomicMin((unsigned int*)p, __float_as_uint(v));
}

// ---------------- edge dtype detect ----------------
__global__ void detect_dtype(const int* __restrict__ ei32) {
    __shared__ int sbad;
    if (threadIdx.x == 0) sbad = 0;
    __syncthreads();
    int bad = 0;
    for (int i = threadIdx.x; i < 1024; i += 256)
        if (ei32[2 * i + 1] != 0) bad = 1;
    if (bad) atomicOr(&sbad, 1);
    __syncthreads();
    if (threadIdx.x == 0) g_is64 = sbad ? 0 : 1;
}

__global__ void zero_cnt() {
    int i = blockIdx.x * blockDim.x + threadIdx.x;
    if (i < N_NODES) g_cnt[i] = 0;
}

// edge prep + histogram of dst
__global__ void prep_edges(const void* __restrict__ ei) {
    int i = blockIdx.x * blockDim.x + threadIdx.x;
    if (i < N_EDGES) {
        int s, d;
        if (g_is64) {
            const long long* p = (const long long*)ei;
            s = (int)p[i];
            d = (int)p[N_EDGES + i];
        } else {
            const int* p = (const int*)ei;
            s = p[i];
            d = p[N_EDGES + i];
        }
        g_es0[i] = s;
        g_ed0[i] = d;
        atomicAdd(&g_cnt[d], 1);
    } else if (i < E_TOT) {
        int n = i - N_EDGES;
        g_es0[i] = n;
        g_ed0[i] = n;
        atomicAdd(&g_cnt[n], 1);
    }
}

// single-block exclusive scan of g_cnt -> g_pos
__global__ void scan_kernel() {
    __shared__ int part[1024];
    int t = threadIdx.x;
    int s = 0;
    int base = t * 10;
    if (t < 1000) {
#pragma unroll
        for (int i = 0; i < 10; i++) s += g_cnt[base + i];
    }
    part[t] = s;
    __syncthreads();
    for (int off = 1; off < 1024; off <<= 1) {
        int v = part[t];
        if (t >= off) v += part[t - off];
        __syncthreads();
        part[t] = v;
        __syncthreads();
    }
    int excl = (t == 0) ? 0 : part[t - 1];
    if (t < 1000) {
        int run = excl;
#pragma unroll
        for (int i = 0; i < 10; i++) {
            int c = g_cnt[base + i];
            g_pos[base + i] = run;
            run += c;
        }
    }
}

__global__ void scatter_kernel() {
    int i = blockIdx.x * blockDim.x + threadIdx.x;
    if (i < E_TOT) {
        int d = g_ed0[i];
        int p = atomicAdd(&g_pos[d], 1);
        g_es[p] = g_es0[i];
        g_ed[p] = d;
    }
}

// ---------------- embed: h0 = x@W_emb + b ----------------
__global__ void embed_kernel(const float* __restrict__ x, const float* __restrict__ W,
                             const float* __restrict__ b, float* __restrict__ h) {
    __shared__ float sx[16][64];
    int n0 = blockIdx.x * 16;
    for (int i = threadIdx.x; i < 16 * 64; i += 128)
        sx[i >> 6][i & 63] = x[n0 * 64 + i];
    __syncthreads();
    int c = threadIdx.x;
    float bc = b[c];
    for (int n = 0; n < 16; n++) {
        float acc = bc;
#pragma unroll 16
        for (int k = 0; k < 64; k++) acc = fmaf(sx[n][k], W[k * 128 + c], acc);
        h[(n0 + n) * 128 + c] = acc;
    }
}

// ---------------- node transform (128 thr, 8 nodes/block -> 1250 blocks) ----------------
__global__ void node_transform(const float* __restrict__ h, const float* __restrict__ W1l,
                               const float* __restrict__ b1l, float* __restrict__ A,
                               float* __restrict__ B, float* __restrict__ out_init) {
    __shared__ float sh[8][128];
    int n0 = blockIdx.x * 8;
    for (int i = threadIdx.x; i < 8 * 128; i += 128)
        sh[i >> 7][i & 127] = h[n0 * 128 + i];
    __syncthreads();
    int c = threadIdx.x;
    float a[8], bb[8];
    float bc = b1l[c];
#pragma unroll
    for (int n = 0; n < 8; n++) { a[n] = bc; bb[n] = 0.f; }
    for (int k = 0; k < 128; k++) {
        float wa = W1l[k * 128 + c];
        float wb = W1l[(k + 128) * 128 + c];
        float wd = wa - wb;
#pragma unroll
        for (int n = 0; n < 8; n++) {
            float hv = sh[n][k];
            a[n]  = fmaf(hv, wd, a[n]);
            bb[n] = fmaf(hv, wb, bb[n]);
        }
    }
#pragma unroll
    for (int n = 0; n < 8; n++) {
        int r = (n0 + n) * 128 + c;
        A[r] = a[n];
        B[r] = bb[n];
        out_init[r] = NEG_INF;
    }
}

// ---------------- persistent edge phase (R12 structure: best verified) ----------------
__global__ __launch_bounds__(THREADS_EDGE, 1)
void edge_persist(const float* __restrict__ A, const float* __restrict__ B,
                  const float* __restrict__ W2l, const float* __restrict__ b2l,
                  const int* __restrict__ es, const int* __restrict__ ed,
                  float* __restrict__ hout) {
    extern __shared__ __align__(16) char sm[];
    __half* sW   = (__half*)(sm + O_W);
    float* sD    = (float*)(sm + O_D);
    int*   sDst  = (int*)(sm + O_DST);     // [2][128]
    float* sBias = (float*)(sm + O_BIAS);

    int tid = threadIdx.x;
    int lane = tid & 31;
    int w = tid >> 5;

    uint32_t smb = (uint32_t)__cvta_generic_to_shared(sm);

    // one-time: W2^T into fp16: sW[n][k]
    for (int i = tid; i < H * H; i += THREADS_EDGE) {
        int k = i >> 7, n = i & 127;
        sW[n * LDW + k] = __float2half_rn(W2l[i]);
    }
    if (tid < 128) sBias[tid] = b2l[tid];
    __syncthreads();

    bool is_consumer = (w < 8);

    // consumer mapping: er = w>>1 edges [er*32,+32); nc = w&1 cols [nc*64,+64)
    int er = w >> 1;
    int nc = w & 1;
    int g  = lane >> 2;
    int t2 = (lane & 3) * 2;

    // A ldmatrix lane addresses
    uint32_t aoff0 = ((uint32_t)((er * 32 + (lane & 15)) * LDZ + (lane >> 4) * 8)) * 2u;
    uint32_t aoff1 = aoff0 + 16u * LDZ * 2u;
    // B x4 lane addresses: lanes 0-15 -> j slab, lanes 16-31 -> j+1 slab (+8 rows)
    uint32_t brow4 = (uint32_t)(nc * 64 + (lane & 7) + ((lane >> 4) & 1) * 8);
    uint32_t bkh   = (uint32_t)((lane >> 3) & 1) * 8u;
    uint32_t bwoff = smb + O_W + (brow4 * LDW + bkh) * 2u;

    // producer identity: threads 256..383 -> 128 producers, 1 per edge
    int pe = tid - 256;

    auto build = [&](int t, int buf) {
        int ee = t * TE + pe;
        bool vld = ee < E_TOT;
        int d = vld ? __ldg(&ed[ee]) : 0;
        int s = vld ? __ldg(&es[ee]) : 0;
        sDst[buf * 128 + pe] = vld ? d : -1;
        const float4* pa = (const float4*)(A + (size_t)d * 128);
        const float4* pb = (const float4*)(B + (size_t)s * 128);
        __half* sZ = (__half*)(sm + O_Z0 + (uint32_t)buf * ZBUF_BYTES);
#pragma unroll
        for (int i = 0; i < 16; i++) {
            float4 a0 = __ldg(pa + 2 * i), a1 = __ldg(pa + 2 * i + 1);
            float4 b0 = __ldg(pb + 2 * i), b1 = __ldg(pb + 2 * i + 1);
            float v0 = 0.f, v1 = 0.f, v2 = 0.f, v3 = 0.f;
            float v4 = 0.f, v5 = 0.f, v6 = 0.f, v7 = 0.f;
            if (vld) {
                v0 = fmaxf(a0.x + b0.x, 0.f);
                v1 = fmaxf(a0.y + b0.y, 0.f);
                v2 = fmaxf(a0.z + b0.z, 0.f);
                v3 = fmaxf(a0.w + b0.w, 0.f);
                v4 = fmaxf(a1.x + b1.x, 0.f);
                v5 = fmaxf(a1.y + b1.y, 0.f);
                v6 = fmaxf(a1.z + b1.z, 0.f);
                v7 = fmaxf(a1.w + b1.w, 0.f);
            }
            __half2 h0 = __floats2half2_rn(v0, v1);
            __half2 h1 = __floats2half2_rn(v2, v3);
            __half2 h2 = __floats2half2_rn(v4, v5);
            __half2 h3 = __floats2half2_rn(v6, v7);
            uint4 pk;
            pk.x = *(uint32_t*)&h0;
            pk.y = *(uint32_t*)&h1;
            pk.z = *(uint32_t*)&h2;
            pk.w = *(uint32_t*)&h3;
            *(uint4*)(sZ + pe * LDZ + i * 8) = pk;
        }
    };

    auto gemm = [&](int buf) {
        uint32_t zbase = smb + O_Z0 + (uint32_t)buf * ZBUF_BYTES;
        float acc[2][8][4];
#pragma unroll
        for (int f = 0; f < 2; f++)
#pragma unroll
            for (int j = 0; j < 8; j++)
#pragma unroll
                for (int r = 0; r < 4; r++) acc[f][j][r] = 0.f;

#pragma unroll
        for (int k0 = 0; k0 < 8; k0++) {
            uint32_t a0[4], a1[4];
            ldsm_x4(a0[0], a0[1], a0[2], a0[3], zbase + aoff0 + (uint32_t)k0 * 32u);
            ldsm_x4(a1[0], a1[1], a1[2], a1[3], zbase + aoff1 + (uint32_t)k0 * 32u);
#pragma unroll
            for (int j = 0; j < 8; j += 2) {
                uint32_t jb = (uint32_t)(j * 8 * LDW * 2) + (uint32_t)k0 * 32u;
                uint32_t b0, b1, b2, b3;
                ldsm_x4(b0, b1, b2, b3, bwoff + jb);
                mma16816(acc[0][j], a0[0], a0[1], a0[2], a0[3], b0, b1);
                mma16816(acc[1][j], a1[0], a1[1], a1[2], a1[3], b0, b1);
                mma16816(acc[0][j + 1], a0[0], a0[1], a0[2], a0[3], b2, b3);
                mma16816(acc[1][j + 1], a1[0], a1[1], a1[2], a1[3], b2, b3);
            }
        }
#pragma unroll
        for (int f = 0; f < 2; f++) {
            int r0 = er * 32 + f * 16 + g;
#pragma unroll
            for (int j = 0; j < 8; j++) {
                int c = nc * 64 + j * 8 + t2;
                *(float2*)(sD + r0 * LDD + c)       = make_float2(acc[f][j][0], acc[f][j][1]);
                *(float2*)(sD + (r0 + 8) * LDD + c) = make_float2(acc[f][j][2], acc[f][j][3]);
            }
        }
    };

    // consumer epilogue: 256 thr = 64 channel-pairs x 4 quarters of 32 edges
    auto epilogue = [&](int buf) {
        int cp = tid & 63;
        int qq = tid >> 6;          // 0..3 for tid<256
        float2 bias2 = *(float2*)(sBias + cp * 2);
        const int* dstb = sDst + buf * 128;
        int cur = dstb[32 * qq];
        float r0 = NEG_INF, r1 = NEG_INF;
#pragma unroll 4
        for (int ee = 32 * qq; ee < 32 * qq + 32; ee++) {
            int d = dstb[ee];
            float2 v = *(float2*)(sD + ee * LDD + cp * 2);
            v.x += bias2.x;
            v.y += bias2.y;
            if (d != cur) {
                if (cur >= 0) {
                    float* p = hout + (size_t)cur * 128 + cp * 2;
                    atomic_fmax(p, r0);
                    atomic_fmax(p + 1, r1);
                }
                cur = d;
                r0 = v.x;
                r1 = v.y;
            } else {
                r0 = fmaxf(r0, v.x);
                r1 = fmaxf(r1, v.y);
            }
        }
        if (cur >= 0) {
            float* p = hout + (size_t)cur * 128 + cp * 2;
            atomic_fmax(p, r0);
            atomic_fmax(p + 1, r1);
        }
    };

    // prologue: producer builds first tile into buf 0
    if (!is_consumer && blockIdx.x < NT_TILES) build(blockIdx.x, 0);
    __syncthreads();

    int it = 0;
    for (int t = blockIdx.x; t < NT_TILES; t += GRID_EDGE, it++) {
        int p = it & 1;
        if (is_consumer) {
            gemm(p);
            asm volatile("bar.sync 1, 256;" ::: "memory");   // sD ready among consumers
            epilogue(p);
        } else {
            int tn = t + GRID_EDGE;
            if (tn < NT_TILES) build(tn, 1 - p);
        }
        __syncthreads();
    }
}

// ---------------- final: out = h@W_fc + b ----------------
__global__ void final_kernel(const float* __restrict__ h, const float* __restrict__ W,
                             const float* __restrict__ b, float* __restrict__ out) {
    __shared__ float sh[16][128];
    int n0 = blockIdx.x * 16;
    for (int i = threadIdx.x; i < 16 * 128; i += 128)
        sh[i >> 7][i & 127] = h[n0 * 128 + i];
    __syncthreads();
    int c = threadIdx.x;
    float bc = b[c];
    for (int n = 0; n < 16; n++) {
        float acc = bc;
#pragma unroll 8
        for (int k = 0; k < 128; k++) acc = fmaf(sh[n][k], W[k * 128 + c], acc);
        out[(n0 + n) * 128 + c] = acc;
    }
}

extern "C" void kernel_launch(void* const* d_in, const int* in_sizes, int n_in,
                              void* d_out, int out_size) {
    const float* x    = (const float*)d_in[0];
    const void*  ei   = d_in[1];
    const float* Wemb = (const float*)d_in[2];
    const float* bemb = (const float*)d_in[3];
    const float* W1   = (const float*)d_in[4];
    const float* b1   = (const float*)d_in[5];
    const float* W2   = (const float*)d_in[6];
    const float* b2   = (const float*)d_in[7];
    const float* Wfc  = (const float*)d_in[8];
    const float* bfc  = (const float*)d_in[9];
    float* out = (float*)d_out;

    float *buf0, *buf1, *Ap, *Bp;
    int *es, *ed;
    cudaGetSymbolAddress((void**)&buf0, g_buf0);
    cudaGetSymbolAddress((void**)&buf1, g_buf1);
    cudaGetSymbolAddress((void**)&Ap,   g_A);
    cudaGetSymbolAddress((void**)&Bp,   g_B);
    cudaGetSymbolAddress((void**)&es,   g_es);
    cudaGetSymbolAddress((void**)&ed,   g_ed);

    cudaFuncSetAttribute(edge_persist, cudaFuncAttributeMaxDynamicSharedMemorySize,
                         SMEM_EDGE_BYTES);

    detect_dtype<<<1, 256>>>((const int*)ei);
    zero_cnt<<<(N_NODES + 255) / 256, 256>>>();
    prep_edges<<<(E_TOT + 255) / 256, 256>>>(ei);
    scan_kernel<<<1, 1024>>>();
    scatter_kernel<<<(E_TOT + 255) / 256, 256>>>();
    embed_kernel<<<N_NODES / 16, 128>>>(x, Wemb, bemb, buf0);

    float* hin = buf0;
    float* hout = buf1;
    for (int l = 0; l < NUM_LAYERS; l++) {
        node_transform<<<N_NODES / 8, 128>>>(hin, W1 + l * 2 * H * H, b1 + l * H,
                                             Ap, Bp, hout);
        edge_persist<<<GRID_EDGE, THREADS_EDGE, SMEM_EDGE_BYTES>>>(Ap, Bp, W2 + l * H * H,
                                                                   b2 + l * H, es, ed, hout);
        float* t = hin; hin = hout; hout = t;
    }
    final_kernel<<<N_NODES / 16, 128>>>(hin, Wfc, bfc, out);
}